// round 10
// baseline (speedup 1.0000x reference)
#include <cuda_runtime.h>
#include <cstdint>

#define NN   100000
#define EE   1600000
#define FIN  128
#define HH   128
#define OUTC 64

// ---------------- scratch (no allocation allowed) ----------------
__device__ __align__(16) int   g_cnt[NN];
__device__ __align__(16) int   g_rowptr[NN + 1];
__device__ __align__(16) int   g_cursor[NN];
__device__ __align__(16) int   g_bsum[256];
__device__ __align__(16) float g_dinv[NN];
__device__ __align__(16) int   g_csr_src[EE];
__device__ __align__(16) float g_t[(size_t)NN * HH];    // GEMM output (dinv-scaled)
__device__ __align__(16) float g_h[(size_t)NN * HH];    // layer activation

// ================= CSR construction =================
__global__ void k_zero(int n) {
    int i = blockIdx.x * blockDim.x + threadIdx.x;
    if (i < n) g_cnt[i] = 0;
}
__global__ void k_count(const int* __restrict__ dst, int e) {
    int i = blockIdx.x * blockDim.x + threadIdx.x;
    if (i < e) atomicAdd(&g_cnt[dst[i]], 1);
}
__global__ void k_scan1(int n) {
    __shared__ int sh[1024];
    int tid = threadIdx.x;
    int i = blockIdx.x * 1024 + tid;
    int v = (i < n) ? g_cnt[i] : 0;
    sh[tid] = v;
    __syncthreads();
#pragma unroll
    for (int off = 1; off < 1024; off <<= 1) {
        int t = (tid >= off) ? sh[tid - off] : 0;
        __syncthreads();
        sh[tid] += t;
        __syncthreads();
    }
    if (i < n) {
        g_rowptr[i] = sh[tid] - v;                 // exclusive, local
        g_dinv[i]   = rsqrtf(1.0f + (float)v);     // +1 self-loop
    }
    if (tid == 1023) g_bsum[blockIdx.x] = sh[1023];
}
__global__ void k_scan2(int nb, int n) {
    __shared__ int sh[128];
    int tid = threadIdx.x;
    int v = (tid < nb) ? g_bsum[tid] : 0;
    sh[tid] = v;
    __syncthreads();
#pragma unroll
    for (int off = 1; off < 128; off <<= 1) {
        int t = (tid >= off) ? sh[tid - off] : 0;
        __syncthreads();
        sh[tid] += t;
        __syncthreads();
    }
    if (tid < nb) g_bsum[tid] = sh[tid] - v;
    if (tid == 127) g_rowptr[n] = sh[127];
}
__global__ void k_scan3(int n) {
    int i = blockIdx.x * blockDim.x + threadIdx.x;
    if (i >= n) return;
    int v = g_rowptr[i] + g_bsum[i >> 10];
    g_rowptr[i] = v;
    g_cursor[i] = v;
}
__global__ void k_fill(const int* __restrict__ src, const int* __restrict__ dst, int e) {
    int i = blockIdx.x * blockDim.x + threadIdx.x;
    if (i >= e) return;
    int d = dst[i];
    int pos = atomicAdd(&g_cursor[d], 1);
    g_csr_src[pos] = src[i];
}

// ================= bf16-split helpers =================
// (v0,v1) -> hi=bf16x2(v0,v1) [v0 in low half], lo=bf16x2 of residuals.
__device__ __forceinline__ void pack_split(float2 v, uint32_t& hi, uint32_t& lo) {
    asm("cvt.rn.bf16x2.f32 %0, %1, %2;" : "=r"(hi) : "f"(v.y), "f"(v.x));
    float h0 = __uint_as_float(hi << 16);
    float h1 = __uint_as_float(hi & 0xFFFF0000u);
    float l0 = v.x - h0;
    float l1 = v.y - h1;
    asm("cvt.rn.bf16x2.f32 %0, %1, %2;" : "=r"(lo) : "f"(l1), "f"(l0));
}
__device__ __forceinline__ void mma_bf16(float c[4], const uint32_t a[4], const uint32_t b[2]) {
    asm volatile(
        "mma.sync.aligned.m16n8k16.row.col.f32.bf16.bf16.f32 "
        "{%0,%1,%2,%3}, {%4,%5,%6,%7}, {%8,%9}, {%0,%1,%2,%3};"
        : "+f"(c[0]), "+f"(c[1]), "+f"(c[2]), "+f"(c[3])
        : "r"(a[0]), "r"(a[1]), "r"(a[2]), "r"(a[3]), "r"(b[0]), "r"(b[1]));
}

// ================= GEMM: g_t[M,DOUT] = dinv[row] * (A[M,128] @ W[128,DOUT]) ==========
// 256 threads (8 warps, 2m x 4n), CTA tile 64 x DOUT. bf16 hi/lo PRE-SPLIT in smem:
// mainloop = pure LDS.32 + MMA (zero conversion ALU). 3 MMAs per k16.
template<int DOUT>
__global__ __launch_bounds__(256, 2)
void k_gemm(const float* __restrict__ Ax, const float* __restrict__ W,
            int M, int from_h) {
    constexpr int DIN = 128;
    constexpr int KP  = DIN / 2;       // 64 k-pairs
    constexpr int AKP = KP + 4;        // 68: A frag banks 4g+t -> conflict-free
    constexpr int WKP = DOUT + 8;      // B frag banks 8t+g -> conflict-free

    extern __shared__ uint32_t smu[];
    uint32_t* Ahi = smu;                         // [64][AKP]
    uint32_t* Alo = Ahi + 64 * AKP;              // [64][AKP]
    uint32_t* Whi = Alo + 64 * AKP;              // [KP][WKP] (row=kpair, col=n)
    uint32_t* Wlo = Whi + KP * WKP;              // [KP][WKP]

    const float* A = from_h ? g_h : Ax;
    int tid  = threadIdx.x;
    int row0 = blockIdx.x * 64;

    // stage + split W: element (kp, n) packs W[2kp][n], W[2kp+1][n]
    for (int i = tid; i < KP * DOUT; i += 256) {
        int kp = i / DOUT;
        int nn = i % DOUT;
        float2 v = make_float2(W[(2 * kp) * DOUT + nn], W[(2 * kp + 1) * DOUT + nn]);
        uint32_t hi, lo;
        pack_split(v, hi, lo);
        Whi[kp * WKP + nn] = hi;
        Wlo[kp * WKP + nn] = lo;
    }
    // stage + split A: element (row, kp) packs A[row][2kp], A[row][2kp+1]
    for (int i = tid; i < 64 * KP; i += 256) {
        int r  = i >> 6;               // KP == 64
        int kp = i & 63;
        int gr = row0 + r;
        float2 v = make_float2(0.f, 0.f);
        if (gr < M) v = ((const float2*)A)[(size_t)gr * KP + kp];
        uint32_t hi, lo;
        pack_split(v, hi, lo);
        Ahi[r * AKP + kp] = hi;
        Alo[r * AKP + kp] = lo;
    }
    __syncthreads();

    int warp = tid >> 5, lane = tid & 31;
    int wm = warp & 1;                 // 0..1
    int wn = warp >> 1;                // 0..3
    int g  = lane >> 2;                // 0..7
    int t  = lane & 3;                 // 0..3
    int mbase = wm * 32;
    int nbase = wn * (DOUT / 4);
    constexpr int NT = DOUT / 32;      // n8-tiles per warp (4 or 2)

    float acc[2][NT][4];
#pragma unroll
    for (int i = 0; i < 2; i++)
#pragma unroll
        for (int j = 0; j < NT; j++)
#pragma unroll
            for (int q = 0; q < 4; q++) acc[i][j][q] = 0.f;

#pragma unroll 2
    for (int kb = 0; kb < KP; kb += 8) {       // k16 per step
        uint32_t ahi[2][4], alo[2][4];
#pragma unroll
        for (int i = 0; i < 2; i++) {
            int base = (mbase + i * 16 + g) * AKP + kb + t;
            ahi[i][0] = Ahi[base];
            ahi[i][1] = Ahi[base + 8 * AKP];
            ahi[i][2] = Ahi[base + 4];
            ahi[i][3] = Ahi[base + 8 * AKP + 4];
            alo[i][0] = Alo[base];
            alo[i][1] = Alo[base + 8 * AKP];
            alo[i][2] = Alo[base + 4];
            alo[i][3] = Alo[base + 8 * AKP + 4];
        }
        uint32_t bhi[NT][2], blo[NT][2];
#pragma unroll
        for (int j = 0; j < NT; j++) {
            int col = nbase + j * 8 + g;
            int b0 = (kb + t) * WKP + col;
            int b1 = (kb + 4 + t) * WKP + col;
            bhi[j][0] = Whi[b0];
            bhi[j][1] = Whi[b1];
            blo[j][0] = Wlo[b0];
            blo[j][1] = Wlo[b1];
        }
#pragma unroll
        for (int i = 0; i < 2; i++)
#pragma unroll
            for (int j = 0; j < NT; j++) {
                mma_bf16(acc[i][j], ahi[i], bhi[j]);
                mma_bf16(acc[i][j], ahi[i], blo[j]);
                mma_bf16(acc[i][j], alo[i], bhi[j]);
            }
    }

    // epilogue: scale by dinv, store float2 pairs
#pragma unroll
    for (int i = 0; i < 2; i++) {
        int r_lo = row0 + mbase + i * 16 + g;
        int r_hi = r_lo + 8;
        float s_lo = (r_lo < M) ? g_dinv[r_lo] : 0.f;
        float s_hi = (r_hi < M) ? g_dinv[r_hi] : 0.f;
#pragma unroll
        for (int j = 0; j < NT; j++) {
            int col = nbase + j * 8 + 2 * t;
            if (r_lo < M)
                *(float2*)&g_t[(size_t)r_lo * DOUT + col] =
                    make_float2(s_lo * acc[i][j][0], s_lo * acc[i][j][1]);
            if (r_hi < M)
                *(float2*)&g_t[(size_t)r_hi * DOUT + col] =
                    make_float2(s_hi * acc[i][j][2], s_hi * acc[i][j][3]);
        }
    }
}

// ================= Aggregation (warp per node), fused epilogue =================
// acc = t[i] + sum_s t[s]  (t pre-scaled by dinv_src);  res = dinv_i*acc + bias
template<int DOUT, int MODE>
__global__ void k_agg(const float* __restrict__ bias, float* __restrict__ out, int n) {
    int w    = (blockIdx.x * blockDim.x + threadIdx.x) >> 5;
    int lane = threadIdx.x & 31;
    if (w >= n) return;
    constexpr int VF = DOUT / 32;

    float acc[VF];
    {
        const float* p = g_t + (size_t)w * DOUT + lane * VF;
        if (VF == 4) { float4 v = *(const float4*)p; acc[0]=v.x; acc[1]=v.y; acc[2]=v.z; acc[3]=v.w; }
        else         { float2 v = *(const float2*)p; acc[0]=v.x; acc[1]=v.y; }
    }

    int beg = g_rowptr[w], end = g_rowptr[w + 1];
    for (int jb = beg; jb < end; jb += 32) {
        int myj = jb + lane;
        int ms  = (myj < end) ? g_csr_src[myj] : 0;
        int cnt = min(32, end - jb);
        int k = 0;
        for (; k + 4 <= cnt; k += 4) {
            int s0 = __shfl_sync(0xffffffffu, ms, k);
            int s1 = __shfl_sync(0xffffffffu, ms, k + 1);
            int s2 = __shfl_sync(0xffffffffu, ms, k + 2);
            int s3 = __shfl_sync(0xffffffffu, ms, k + 3);
            if (VF == 4) {
                float4 v0 = *(const float4*)(g_t + (size_t)s0 * DOUT + lane * 4);
                float4 v1 = *(const float4*)(g_t + (size_t)s1 * DOUT + lane * 4);
                float4 v2 = *(const float4*)(g_t + (size_t)s2 * DOUT + lane * 4);
                float4 v3 = *(const float4*)(g_t + (size_t)s3 * DOUT + lane * 4);
                acc[0] += (v0.x + v1.x) + (v2.x + v3.x);
                acc[1] += (v0.y + v1.y) + (v2.y + v3.y);
                acc[2] += (v0.z + v1.z) + (v2.z + v3.z);
                acc[3] += (v0.w + v1.w) + (v2.w + v3.w);
            } else {
                float2 v0 = *(const float2*)(g_t + (size_t)s0 * DOUT + lane * 2);
                float2 v1 = *(const float2*)(g_t + (size_t)s1 * DOUT + lane * 2);
                float2 v2 = *(const float2*)(g_t + (size_t)s2 * DOUT + lane * 2);
                float2 v3 = *(const float2*)(g_t + (size_t)s3 * DOUT + lane * 2);
                acc[0] += (v0.x + v1.x) + (v2.x + v3.x);
                acc[1] += (v0.y + v1.y) + (v2.y + v3.y);
            }
        }
        for (; k < cnt; k++) {
            int s = __shfl_sync(0xffffffffu, ms, k);
            if (VF == 4) {
                float4 v = *(const float4*)(g_t + (size_t)s * DOUT + lane * 4);
                acc[0] += v.x; acc[1] += v.y; acc[2] += v.z; acc[3] += v.w;
            } else {
                float2 v = *(const float2*)(g_t + (size_t)s * DOUT + lane * 2);
                acc[0] += v.x; acc[1] += v.y;
            }
        }
    }

    float di = g_dinv[w];
    if (MODE == 0) {
        float4 bb = ((const float4*)bias)[lane];
        float4 r;
        r.x = fmaxf(fmaf(di, acc[0], bb.x), 0.f);
        r.y = fmaxf(fmaf(di, acc[1], bb.y), 0.f);
        r.z = fmaxf(fmaf(di, acc[2], bb.z), 0.f);
        r.w = fmaxf(fmaf(di, acc[3], bb.w), 0.f);
        *(float4*)(g_h + (size_t)w * DOUT + lane * 4) = r;
    } else {
        float2 bb = ((const float2*)bias)[lane];
        float vx = fmaf(di, acc[0], bb.x);
        float vy = fmaf(di, acc[1], bb.y);
        float m = fmaxf(vx, vy);
#pragma unroll
        for (int o = 16; o; o >>= 1) m = fmaxf(m, __shfl_xor_sync(0xffffffffu, m, o));
        float sum = expf(vx - m) + expf(vy - m);
#pragma unroll
        for (int o = 16; o; o >>= 1) sum += __shfl_xor_sync(0xffffffffu, sum, o);
        float lse = m + logf(sum);
        *(float2*)(out + (size_t)w * 64 + lane * 2) = make_float2(vx - lse, vy - lse);
    }
}

// ================= launch =================
extern "C" void kernel_launch(void* const* d_in, const int* in_sizes, int n_in,
                              void* d_out, int out_size) {
    const float* x   = (const float*)d_in[0];
    const int*   ei  = (const int*)d_in[1];     // int32 (JAX x64 disabled)
    const float* W1  = (const float*)d_in[2];
    const float* b1  = (const float*)d_in[3];
    const float* W2  = (const float*)d_in[4];
    const float* b2  = (const float*)d_in[5];
    const float* W3  = (const float*)d_in[6];
    const float* b3  = (const float*)d_in[7];
    float* out = (float*)d_out;

    int n = in_sizes[0] / FIN;
    int e = in_sizes[1] / 2;
    const int* srcp = ei;
    const int* dstp = ei + e;

    const int smem128 = (64 * (64 + 4) * 2 + 64 * (HH   + 8) * 2) * 4; // ~102 KB -> 2 CTA/SM
    const int smem64  = (64 * (64 + 4) * 2 + 64 * (OUTC + 8) * 2) * 4; // ~70 KB  -> 3 CTA/SM
    cudaFuncSetAttribute(k_gemm<HH>,   cudaFuncAttributeMaxDynamicSharedMemorySize, smem128);
    cudaFuncSetAttribute(k_gemm<OUTC>, cudaFuncAttributeMaxDynamicSharedMemorySize, smem64);

    int nb_scan = (n + 1023) >> 10;
    int gemm_blocks = (n + 63) / 64;
    int agg_blocks  = (int)(((long long)n * 32 + 255) / 256);

    // CSR build + dinv (sequential; launch #4 = profiled gemm1, which only needs dinv)
    k_zero <<<(n + 255) / 256, 256>>>(n);                  // 1
    k_count<<<(e + 255) / 256, 256>>>(dstp, e);            // 2
    k_scan1<<<nb_scan, 1024>>>(n);                         // 3 (dinv ready)
    k_gemm<HH><<<gemm_blocks, 256, smem128>>>(x, W1, n, 0);// 4 <-- profiled
    k_scan2<<<1, 128>>>(nb_scan, n);                       // 5
    k_scan3<<<(n + 255) / 256, 256>>>(n);                  // 6
    k_fill <<<(e + 255) / 256, 256>>>(srcp, dstp, e);      // 7

    k_agg<HH, 0><<<agg_blocks, 256>>>(b1, nullptr, n);
    k_gemm<HH><<<gemm_blocks, 256, smem128>>>(x, W2, n, 1);
    k_agg<HH, 0><<<agg_blocks, 256>>>(b2, nullptr, n);
    k_gemm<OUTC><<<gemm_blocks, 256, smem64>>>(x, W3, n, 1);
    k_agg<OUTC, 1><<<agg_blocks, 256>>>(b3, out, n);
}

// round 11
// speedup vs baseline: 1.0995x; 1.0995x over previous
#include <cuda_runtime.h>
#include <cstdint>

#define NN   100000
#define EE   1600000
#define FIN  128
#define HH   128
#define OUTC 64

// ---------------- scratch (no allocation allowed) ----------------
__device__ __align__(16) int   g_cnt[NN];
__device__ __align__(16) int   g_rowptr[NN + 1];
__device__ __align__(16) int   g_cursor[NN];
__device__ __align__(16) int   g_bsum[256];
__device__ __align__(16) float g_dinv[NN];
__device__ __align__(16) int   g_csr_src[EE];
__device__ __align__(16) float g_t[(size_t)NN * HH];    // GEMM output (dinv-scaled)
__device__ __align__(16) float g_h[(size_t)NN * HH];    // layer activation

// ================= CSR construction =================
__global__ void k_zero(int n) {
    int i = blockIdx.x * blockDim.x + threadIdx.x;
    if (i < n) g_cnt[i] = 0;
}
__global__ void k_count(const int* __restrict__ dst, int e) {
    int i = blockIdx.x * blockDim.x + threadIdx.x;
    if (i < e) atomicAdd(&g_cnt[dst[i]], 1);
}
__global__ void k_scan1(int n) {
    __shared__ int sh[1024];
    int tid = threadIdx.x;
    int i = blockIdx.x * 1024 + tid;
    int v = (i < n) ? g_cnt[i] : 0;
    sh[tid] = v;
    __syncthreads();
#pragma unroll
    for (int off = 1; off < 1024; off <<= 1) {
        int t = (tid >= off) ? sh[tid - off] : 0;
        __syncthreads();
        sh[tid] += t;
        __syncthreads();
    }
    if (i < n) {
        g_rowptr[i] = sh[tid] - v;                 // exclusive, local
        g_dinv[i]   = rsqrtf(1.0f + (float)v);     // +1 self-loop
    }
    if (tid == 1023) g_bsum[blockIdx.x] = sh[1023];
}
__global__ void k_scan2(int nb, int n) {
    __shared__ int sh[128];
    int tid = threadIdx.x;
    int v = (tid < nb) ? g_bsum[tid] : 0;
    sh[tid] = v;
    __syncthreads();
#pragma unroll
    for (int off = 1; off < 128; off <<= 1) {
        int t = (tid >= off) ? sh[tid - off] : 0;
        __syncthreads();
        sh[tid] += t;
        __syncthreads();
    }
    if (tid < nb) g_bsum[tid] = sh[tid] - v;
    if (tid == 127) g_rowptr[n] = sh[127];
}
__global__ void k_scan3(int n) {
    int i = blockIdx.x * blockDim.x + threadIdx.x;
    if (i >= n) return;
    int v = g_rowptr[i] + g_bsum[i >> 10];
    g_rowptr[i] = v;
    g_cursor[i] = v;
}
__global__ void k_fill(const int* __restrict__ src, const int* __restrict__ dst, int e) {
    int i = blockIdx.x * blockDim.x + threadIdx.x;
    if (i >= e) return;
    int d = dst[i];
    int pos = atomicAdd(&g_cursor[d], 1);
    g_csr_src[pos] = src[i];
}

// ================= bf16-split helpers =================
// (v0,v1) -> hi=bf16x2(v0,v1) [v0 in low half], lo=bf16x2 of residuals.
__device__ __forceinline__ void pack_split(float2 v, uint32_t& hi, uint32_t& lo) {
    asm("cvt.rn.bf16x2.f32 %0, %1, %2;" : "=r"(hi) : "f"(v.y), "f"(v.x));
    float h0 = __uint_as_float(hi << 16);
    float h1 = __uint_as_float(hi & 0xFFFF0000u);
    float l0 = v.x - h0;
    float l1 = v.y - h1;
    asm("cvt.rn.bf16x2.f32 %0, %1, %2;" : "=r"(lo) : "f"(l1), "f"(l0));
}
__device__ __forceinline__ void mma_bf16(float c[4], const uint32_t a[4], const uint32_t b[2]) {
    asm volatile(
        "mma.sync.aligned.m16n8k16.row.col.f32.bf16.bf16.f32 "
        "{%0,%1,%2,%3}, {%4,%5,%6,%7}, {%8,%9}, {%0,%1,%2,%3};"
        : "+f"(c[0]), "+f"(c[1]), "+f"(c[2]), "+f"(c[3])
        : "r"(a[0]), "r"(a[1]), "r"(a[2]), "r"(a[3]), "r"(b[0]), "r"(b[1]));
}

// ================= GEMM: g_t[M,DOUT] = dinv[row] * (A[M,128] @ W[128,DOUT]) ==========
// 256 threads (8 warps, 2m x 4n), CTA tile 64 x DOUT. bf16-split INLINE in mainloop
// (round-9 measured-best mainloop), dinv scaling in epilogue. 3 MMAs per k16.
template<int DOUT>
__global__ __launch_bounds__(256, 2)
void k_gemm(const float* __restrict__ Ax, const float* __restrict__ W,
            int M, int from_h) {
    constexpr int DIN = 128;
    constexpr int AST = DIN + 8;      // 136: LDS.64 A-frag conflict-free
    constexpr int WST = DOUT + 4;     // LDS.32 B-frag conflict-free
    constexpr int NT  = DOUT / 32;    // n8-tiles per warp (4 or 2)

    extern __shared__ float sm[];
    float* As = sm;                   // [64][AST]
    float* Ws = sm + 64 * AST;        // [128][WST]  row=k, col=n

    const float* A = from_h ? g_h : Ax;
    int tid  = threadIdx.x;
    int row0 = blockIdx.x * 64;

    for (int i = tid; i < DIN * (DOUT / 4); i += 256) {
        int r  = i / (DOUT / 4);
        int c4 = i % (DOUT / 4);
        *(float4*)(Ws + r * WST + c4 * 4) = ((const float4*)W)[i];
    }
    for (int i = tid; i < 64 * 32; i += 256) {
        int r  = i >> 5;
        int c4 = i & 31;
        int gr = row0 + r;
        float4 v = make_float4(0.f, 0.f, 0.f, 0.f);
        if (gr < M) v = ((const float4*)A)[(size_t)gr * 32 + c4];
        *(float4*)(As + r * AST + c4 * 4) = v;
    }
    __syncthreads();

    int warp = tid >> 5, lane = tid & 31;
    int wm = warp & 1;                 // 0..1
    int wn = warp >> 1;                // 0..3
    int g  = lane >> 2;                // 0..7
    int t  = lane & 3;                 // 0..3
    int mbase = wm * 32;
    int nbase = wn * (DOUT / 4);

    float acc[2][NT][4];
#pragma unroll
    for (int i = 0; i < 2; i++)
#pragma unroll
        for (int j = 0; j < NT; j++)
#pragma unroll
            for (int q = 0; q < 4; q++) acc[i][j][q] = 0.f;

#pragma unroll 2
    for (int kk = 0; kk < DIN; kk += 16) {
        uint32_t ahi[2][4], alo[2][4];
#pragma unroll
        for (int i = 0; i < 2; i++) {
            const float* p = As + (mbase + i * 16 + g) * AST + kk + 2 * t;
            float2 v00 = *(const float2*)(p);                 // a0: row g,   k 2t..2t+1
            float2 v10 = *(const float2*)(p + 8 * AST);       // a1: row g+8
            float2 v01 = *(const float2*)(p + 8);             // a2: row g,   k+8
            float2 v11 = *(const float2*)(p + 8 * AST + 8);   // a3: row g+8, k+8
            pack_split(v00, ahi[i][0], alo[i][0]);
            pack_split(v10, ahi[i][1], alo[i][1]);
            pack_split(v01, ahi[i][2], alo[i][2]);
            pack_split(v11, ahi[i][3], alo[i][3]);
        }
        uint32_t bhi[NT][2], blo[NT][2];
#pragma unroll
        for (int j = 0; j < NT; j++) {
            const float* q = Ws + (kk + 2 * t) * WST + nbase + j * 8 + g;
            float2 u0 = make_float2(q[0], q[WST]);            // b0: k 2t, 2t+1
            float2 u1 = make_float2(q[8 * WST], q[9 * WST]);  // b1: k 2t+8, 2t+9
            pack_split(u0, bhi[j][0], blo[j][0]);
            pack_split(u1, bhi[j][1], blo[j][1]);
        }
#pragma unroll
        for (int i = 0; i < 2; i++)
#pragma unroll
            for (int j = 0; j < NT; j++) {
                mma_bf16(acc[i][j], ahi[i], bhi[j]);
                mma_bf16(acc[i][j], ahi[i], blo[j]);
                mma_bf16(acc[i][j], alo[i], bhi[j]);
            }
    }

    // epilogue: scale by dinv, store float2 pairs
#pragma unroll
    for (int i = 0; i < 2; i++) {
        int r_lo = row0 + mbase + i * 16 + g;
        int r_hi = r_lo + 8;
        float s_lo = (r_lo < M) ? g_dinv[r_lo] : 0.f;
        float s_hi = (r_hi < M) ? g_dinv[r_hi] : 0.f;
#pragma unroll
        for (int j = 0; j < NT; j++) {
            int col = nbase + j * 8 + 2 * t;
            if (r_lo < M)
                *(float2*)&g_t[(size_t)r_lo * DOUT + col] =
                    make_float2(s_lo * acc[i][j][0], s_lo * acc[i][j][1]);
            if (r_hi < M)
                *(float2*)&g_t[(size_t)r_hi * DOUT + col] =
                    make_float2(s_hi * acc[i][j][2], s_hi * acc[i][j][3]);
        }
    }
}

// ================= Aggregation (warp per node), fused epilogue =================
// acc = t[i] + sum_s t[s]  (t pre-scaled by dinv_src);  res = dinv_i*acc + bias
template<int DOUT, int MODE>
__global__ void k_agg(const float* __restrict__ bias, float* __restrict__ out, int n) {
    int w    = (blockIdx.x * blockDim.x + threadIdx.x) >> 5;
    int lane = threadIdx.x & 31;
    if (w >= n) return;
    constexpr int VF = DOUT / 32;

    float acc[VF];
    {
        const float* p = g_t + (size_t)w * DOUT + lane * VF;
        if (VF == 4) { float4 v = *(const float4*)p; acc[0]=v.x; acc[1]=v.y; acc[2]=v.z; acc[3]=v.w; }
        else         { float2 v = *(const float2*)p; acc[0]=v.x; acc[1]=v.y; }
    }

    int beg = g_rowptr[w], end = g_rowptr[w + 1];
    for (int jb = beg; jb < end; jb += 32) {
        int myj = jb + lane;
        int ms  = (myj < end) ? g_csr_src[myj] : 0;
        int cnt = min(32, end - jb);
        int k = 0;
        for (; k + 4 <= cnt; k += 4) {
            int s0 = __shfl_sync(0xffffffffu, ms, k);
            int s1 = __shfl_sync(0xffffffffu, ms, k + 1);
            int s2 = __shfl_sync(0xffffffffu, ms, k + 2);
            int s3 = __shfl_sync(0xffffffffu, ms, k + 3);
            if (VF == 4) {
                float4 v0 = *(const float4*)(g_t + (size_t)s0 * DOUT + lane * 4);
                float4 v1 = *(const float4*)(g_t + (size_t)s1 * DOUT + lane * 4);
                float4 v2 = *(const float4*)(g_t + (size_t)s2 * DOUT + lane * 4);
                float4 v3 = *(const float4*)(g_t + (size_t)s3 * DOUT + lane * 4);
                acc[0] += (v0.x + v1.x) + (v2.x + v3.x);
                acc[1] += (v0.y + v1.y) + (v2.y + v3.y);
                acc[2] += (v0.z + v1.z) + (v2.z + v3.z);
                acc[3] += (v0.w + v1.w) + (v2.w + v3.w);
            } else {
                float2 v0 = *(const float2*)(g_t + (size_t)s0 * DOUT + lane * 2);
                float2 v1 = *(const float2*)(g_t + (size_t)s1 * DOUT + lane * 2);
                float2 v2 = *(const float2*)(g_t + (size_t)s2 * DOUT + lane * 2);
                float2 v3 = *(const float2*)(g_t + (size_t)s3 * DOUT + lane * 2);
                acc[0] += (v0.x + v1.x) + (v2.x + v3.x);
                acc[1] += (v0.y + v1.y) + (v2.y + v3.y);
            }
        }
        for (; k < cnt; k++) {
            int s = __shfl_sync(0xffffffffu, ms, k);
            if (VF == 4) {
                float4 v = *(const float4*)(g_t + (size_t)s * DOUT + lane * 4);
                acc[0] += v.x; acc[1] += v.y; acc[2] += v.z; acc[3] += v.w;
            } else {
                float2 v = *(const float2*)(g_t + (size_t)s * DOUT + lane * 2);
                acc[0] += v.x; acc[1] += v.y;
            }
        }
    }

    float di = g_dinv[w];
    if (MODE == 0) {
        float4 bb = ((const float4*)bias)[lane];
        float4 r;
        r.x = fmaxf(fmaf(di, acc[0], bb.x), 0.f);
        r.y = fmaxf(fmaf(di, acc[1], bb.y), 0.f);
        r.z = fmaxf(fmaf(di, acc[2], bb.z), 0.f);
        r.w = fmaxf(fmaf(di, acc[3], bb.w), 0.f);
        *(float4*)(g_h + (size_t)w * DOUT + lane * 4) = r;
    } else {
        float2 bb = ((const float2*)bias)[lane];
        float vx = fmaf(di, acc[0], bb.x);
        float vy = fmaf(di, acc[1], bb.y);
        float m = fmaxf(vx, vy);
#pragma unroll
        for (int o = 16; o; o >>= 1) m = fmaxf(m, __shfl_xor_sync(0xffffffffu, m, o));
        float sum = expf(vx - m) + expf(vy - m);
#pragma unroll
        for (int o = 16; o; o >>= 1) sum += __shfl_xor_sync(0xffffffffu, sum, o);
        float lse = m + logf(sum);
        *(float2*)(out + (size_t)w * 64 + lane * 2) = make_float2(vx - lse, vy - lse);
    }
}

// ================= launch =================
extern "C" void kernel_launch(void* const* d_in, const int* in_sizes, int n_in,
                              void* d_out, int out_size) {
    const float* x   = (const float*)d_in[0];
    const int*   ei  = (const int*)d_in[1];     // int32 (JAX x64 disabled)
    const float* W1  = (const float*)d_in[2];
    const float* b1  = (const float*)d_in[3];
    const float* W2  = (const float*)d_in[4];
    const float* b2  = (const float*)d_in[5];
    const float* W3  = (const float*)d_in[6];
    const float* b3  = (const float*)d_in[7];
    float* out = (float*)d_out;

    int n = in_sizes[0] / FIN;
    int e = in_sizes[1] / 2;
    const int* srcp = ei;
    const int* dstp = ei + e;

    const int smem128 = (64 * (FIN + 8) + 128 * (HH   + 4)) * sizeof(float); // ~100 KB -> 2 CTA/SM
    const int smem64  = (64 * (FIN + 8) + 128 * (OUTC + 4)) * sizeof(float); // ~68 KB  -> 3 CTA/SM
    cudaFuncSetAttribute(k_gemm<HH>,   cudaFuncAttributeMaxDynamicSharedMemorySize, smem128);
    cudaFuncSetAttribute(k_gemm<OUTC>, cudaFuncAttributeMaxDynamicSharedMemorySize, smem64);

    int nb_scan = (n + 1023) >> 10;
    int gemm_blocks = (n + 63) / 64;
    int agg_blocks  = (int)(((long long)n * 32 + 255) / 256);

    // CSR build + dinv (sequential; launch #4 = profiled gemm1, which only needs dinv)
    k_zero <<<(n + 255) / 256, 256>>>(n);                  // 1
    k_count<<<(e + 255) / 256, 256>>>(dstp, e);            // 2
    k_scan1<<<nb_scan, 1024>>>(n);                         // 3 (dinv ready)
    k_gemm<HH><<<gemm_blocks, 256, smem128>>>(x, W1, n, 0);// 4 <-- profiled
    k_scan2<<<1, 128>>>(nb_scan, n);                       // 5
    k_scan3<<<(n + 255) / 256, 256>>>(n);                  // 6
    k_fill <<<(e + 255) / 256, 256>>>(srcp, dstp, e);      // 7

    k_agg<HH, 0><<<agg_blocks, 256>>>(b1, nullptr, n);
    k_gemm<HH><<<gemm_blocks, 256, smem128>>>(x, W2, n, 1);
    k_agg<HH, 0><<<agg_blocks, 256>>>(b2, nullptr, n);
    k_gemm<OUTC><<<gemm_blocks, 256, smem64>>>(x, W3, n, 1);
    k_agg<OUTC, 1><<<agg_blocks, 256>>>(b3, out, n);
}

// round 13
// speedup vs baseline: 1.1457x; 1.0420x over previous
#include <cuda_runtime.h>
#include <cstdint>

#define NN   100000
#define EE   1600000
#define FIN  128
#define HH   128
#define OUTC 64

// ---------------- scratch (no allocation allowed) ----------------
__device__ __align__(16) int   g_cnt[NN];
__device__ __align__(16) int   g_rowptr[NN + 1];
__device__ __align__(16) int   g_cursor[NN];
__device__ __align__(16) int   g_bsum[256];
__device__ __align__(16) float g_dinv[NN];
__device__ __align__(16) int   g_csr_src[EE];
__device__ __align__(16) float g_t[(size_t)NN * HH];          // GEMM output (dinv-scaled)
__device__ __align__(16) uint32_t g_ahi[(size_t)NN * 64];     // activation hi (bf16x2, kp-major)
__device__ __align__(16) uint32_t g_alo[(size_t)NN * 64];     // activation lo
__device__ __align__(16) uint32_t g_whi[64 * HH];             // W pre-split hi [kp][n]
__device__ __align__(16) uint32_t g_wlo[64 * HH];             // W pre-split lo

// ================= CSR construction =================
__global__ void k_zero(int n) {
    int i = blockIdx.x * blockDim.x + threadIdx.x;
    if (i < n) g_cnt[i] = 0;
}
__global__ void k_count(const int* __restrict__ dst, int e) {
    int i = blockIdx.x * blockDim.x + threadIdx.x;
    if (i < e) atomicAdd(&g_cnt[dst[i]], 1);
}
__global__ void k_scan1(int n) {
    __shared__ int sh[1024];
    int tid = threadIdx.x;
    int i = blockIdx.x * 1024 + tid;
    int v = (i < n) ? g_cnt[i] : 0;
    sh[tid] = v;
    __syncthreads();
#pragma unroll
    for (int off = 1; off < 1024; off <<= 1) {
        int t = (tid >= off) ? sh[tid - off] : 0;
        __syncthreads();
        sh[tid] += t;
        __syncthreads();
    }
    if (i < n) {
        g_rowptr[i] = sh[tid] - v;
        g_dinv[i]   = rsqrtf(1.0f + (float)v);
    }
    if (tid == 1023) g_bsum[blockIdx.x] = sh[1023];
}
__global__ void k_scan2(int nb, int n) {
    __shared__ int sh[128];
    int tid = threadIdx.x;
    int v = (tid < nb) ? g_bsum[tid] : 0;
    sh[tid] = v;
    __syncthreads();
#pragma unroll
    for (int off = 1; off < 128; off <<= 1) {
        int t = (tid >= off) ? sh[tid - off] : 0;
        __syncthreads();
        sh[tid] += t;
        __syncthreads();
    }
    if (tid < nb) g_bsum[tid] = sh[tid] - v;
    if (tid == 127) g_rowptr[n] = sh[127];
}
__global__ void k_scan3(int n) {
    int i = blockIdx.x * blockDim.x + threadIdx.x;
    if (i >= n) return;
    int v = g_rowptr[i] + g_bsum[i >> 10];
    g_rowptr[i] = v;
    g_cursor[i] = v;
}
__global__ void k_fill(const int* __restrict__ src, const int* __restrict__ dst, int e) {
    int i = blockIdx.x * blockDim.x + threadIdx.x;
    if (i >= e) return;
    int d = dst[i];
    int pos = atomicAdd(&g_cursor[d], 1);
    g_csr_src[pos] = src[i];
}

// ================= bf16-split helpers =================
__device__ __forceinline__ void pack_split(float2 v, uint32_t& hi, uint32_t& lo) {
    asm("cvt.rn.bf16x2.f32 %0, %1, %2;" : "=r"(hi) : "f"(v.y), "f"(v.x));
    float h0 = __uint_as_float(hi << 16);
    float h1 = __uint_as_float(hi & 0xFFFF0000u);
    float l0 = v.x - h0;
    float l1 = v.y - h1;
    asm("cvt.rn.bf16x2.f32 %0, %1, %2;" : "=r"(lo) : "f"(l1), "f"(l0));
}
__device__ __forceinline__ void mma_bf16(float c[4], const uint32_t a[4], const uint32_t b[2]) {
    asm volatile(
        "mma.sync.aligned.m16n8k16.row.col.f32.bf16.bf16.f32 "
        "{%0,%1,%2,%3}, {%4,%5,%6,%7}, {%8,%9}, {%0,%1,%2,%3};"
        : "+f"(c[0]), "+f"(c[1]), "+f"(c[2]), "+f"(c[3])
        : "r"(a[0]), "r"(a[1]), "r"(a[2]), "r"(a[3]), "r"(b[0]), "r"(b[1]));
}

// ================= W pre-split: g_whi/lo[kp][n] packs W[2kp][n], W[2kp+1][n] ======
template<int DOUT>
__global__ void k_split_w(const float* __restrict__ W) {
    int i = blockIdx.x * blockDim.x + threadIdx.x;
    if (i >= 64 * DOUT) return;
    int kp = i / DOUT;
    int nn = i % DOUT;
    float2 v = make_float2(W[(2 * kp) * DOUT + nn], W[(2 * kp + 1) * DOUT + nn]);
    uint32_t hi, lo;
    pack_split(v, hi, lo);
    g_whi[i] = hi;
    g_wlo[i] = lo;
}

// ============ GEMM layer 1 (reads f32 x, inline split — round-11 form) ============
__global__ __launch_bounds__(256, 2)
void k_gemm1(const float* __restrict__ Ax, const float* __restrict__ W, int M) {
    constexpr int DOUT = HH;
    constexpr int DIN = 128;
    constexpr int AST = DIN + 8;
    constexpr int WST = DOUT + 4;
    constexpr int NT  = DOUT / 32;

    extern __shared__ float sm[];
    float* As = sm;
    float* Ws = sm + 64 * AST;

    int tid  = threadIdx.x;
    int row0 = blockIdx.x * 64;

    for (int i = tid; i < DIN * (DOUT / 4); i += 256) {
        int r  = i / (DOUT / 4);
        int c4 = i % (DOUT / 4);
        *(float4*)(Ws + r * WST + c4 * 4) = ((const float4*)W)[i];
    }
    for (int i = tid; i < 64 * 32; i += 256) {
        int r  = i >> 5;
        int c4 = i & 31;
        int gr = row0 + r;
        float4 v = make_float4(0.f, 0.f, 0.f, 0.f);
        if (gr < M) v = ((const float4*)Ax)[(size_t)gr * 32 + c4];
        *(float4*)(As + r * AST + c4 * 4) = v;
    }
    __syncthreads();

    int warp = tid >> 5, lane = tid & 31;
    int wm = warp & 1;
    int wn = warp >> 1;
    int g  = lane >> 2;
    int t  = lane & 3;
    int mbase = wm * 32;
    int nbase = wn * (DOUT / 4);

    float acc[2][NT][4];
#pragma unroll
    for (int i = 0; i < 2; i++)
#pragma unroll
        for (int j = 0; j < NT; j++)
#pragma unroll
            for (int q = 0; q < 4; q++) acc[i][j][q] = 0.f;

#pragma unroll 2
    for (int kk = 0; kk < DIN; kk += 16) {
        uint32_t ahi[2][4], alo[2][4];
#pragma unroll
        for (int i = 0; i < 2; i++) {
            const float* p = As + (mbase + i * 16 + g) * AST + kk + 2 * t;
            float2 v00 = *(const float2*)(p);
            float2 v10 = *(const float2*)(p + 8 * AST);
            float2 v01 = *(const float2*)(p + 8);
            float2 v11 = *(const float2*)(p + 8 * AST + 8);
            pack_split(v00, ahi[i][0], alo[i][0]);
            pack_split(v10, ahi[i][1], alo[i][1]);
            pack_split(v01, ahi[i][2], alo[i][2]);
            pack_split(v11, ahi[i][3], alo[i][3]);
        }
        uint32_t bhi[NT][2], blo[NT][2];
#pragma unroll
        for (int j = 0; j < NT; j++) {
            const float* q = Ws + (kk + 2 * t) * WST + nbase + j * 8 + g;
            float2 u0 = make_float2(q[0], q[WST]);
            float2 u1 = make_float2(q[8 * WST], q[9 * WST]);
            pack_split(u0, bhi[j][0], blo[j][0]);
            pack_split(u1, bhi[j][1], blo[j][1]);
        }
#pragma unroll
        for (int i = 0; i < 2; i++)
#pragma unroll
            for (int j = 0; j < NT; j++) {
                mma_bf16(acc[i][j], ahi[i], bhi[j]);
                mma_bf16(acc[i][j], ahi[i], blo[j]);
                mma_bf16(acc[i][j], alo[i], bhi[j]);
            }
    }

#pragma unroll
    for (int i = 0; i < 2; i++) {
        int r_lo = row0 + mbase + i * 16 + g;
        int r_hi = r_lo + 8;
        float s_lo = (r_lo < M) ? g_dinv[r_lo] : 0.f;
        float s_hi = (r_hi < M) ? g_dinv[r_hi] : 0.f;
#pragma unroll
        for (int j = 0; j < NT; j++) {
            int col = nbase + j * 8 + 2 * t;
            if (r_lo < M)
                *(float2*)&g_t[(size_t)r_lo * DOUT + col] =
                    make_float2(s_lo * acc[i][j][0], s_lo * acc[i][j][1]);
            if (r_hi < M)
                *(float2*)&g_t[(size_t)r_hi * DOUT + col] =
                    make_float2(s_hi * acc[i][j][2], s_hi * acc[i][j][3]);
        }
    }
}

// ======== GEMM layers 2/3: pre-split bf16 operands, PURE LDS+MMA mainloop =========
// A from g_ahi/g_alo [N][64 kp], W from g_whi/g_wlo [64 kp][DOUT].
template<int DOUT>
__global__ __launch_bounds__(256, 2)
void k_gemm_pre(int M) {
    constexpr int KP  = 64;
    constexpr int AKP = KP + 4;        // 68: frag banks 4g+t -> conflict-free
    constexpr int WKP = DOUT + 8;      // frag banks 8t+g -> conflict-free
    constexpr int NT  = DOUT / 32;

    extern __shared__ uint32_t smu[];
    uint32_t* Ahi = smu;                          // [64][AKP]
    uint32_t* Alo = Ahi + 64 * AKP;
    uint32_t* Whi = Alo + 64 * AKP;               // [KP][WKP]
    uint32_t* Wlo = Whi + KP * WKP;

    int tid  = threadIdx.x;
    int row0 = blockIdx.x * 64;

    // stage W (uint4 copies of pre-split data)
    for (int i = tid; i < KP * (DOUT / 4); i += 256) {
        int kp = i / (DOUT / 4);
        int n4 = i % (DOUT / 4);
        uint4 h = ((const uint4*)g_whi)[(size_t)kp * (DOUT / 4) + n4];
        uint4 l = ((const uint4*)g_wlo)[(size_t)kp * (DOUT / 4) + n4];
        *(uint4*)(Whi + kp * WKP + n4 * 4) = h;
        *(uint4*)(Wlo + kp * WKP + n4 * 4) = l;
    }
    // stage A (uint2 copies of pre-split activations)
    for (int i = tid; i < 64 * 32; i += 256) {
        int r = i >> 5;
        int c = i & 31;                 // 2 kp per c
        int gr = row0 + r;
        uint2 h = make_uint2(0u, 0u), l = make_uint2(0u, 0u);
        if (gr < M) {
            h = ((const uint2*)(g_ahi + (size_t)gr * 64))[c];
            l = ((const uint2*)(g_alo + (size_t)gr * 64))[c];
        }
        *(uint2*)(Ahi + r * AKP + c * 2) = h;
        *(uint2*)(Alo + r * AKP + c * 2) = l;
    }
    __syncthreads();

    int warp = tid >> 5, lane = tid & 31;
    int wm = warp & 1;
    int wn = warp >> 1;
    int g  = lane >> 2;
    int t  = lane & 3;
    int mbase = wm * 32;
    int nbase = wn * (DOUT / 4);

    float acc[2][NT][4];
#pragma unroll
    for (int i = 0; i < 2; i++)
#pragma unroll
        for (int j = 0; j < NT; j++)
#pragma unroll
            for (int q = 0; q < 4; q++) acc[i][j][q] = 0.f;

#pragma unroll 2
    for (int kb = 0; kb < KP; kb += 8) {          // k16 per step
        uint32_t ahi[2][4], alo[2][4];
#pragma unroll
        for (int i = 0; i < 2; i++) {
            int base = (mbase + i * 16 + g) * AKP + kb + t;
            ahi[i][0] = Ahi[base];
            ahi[i][1] = Ahi[base + 8 * AKP];
            ahi[i][2] = Ahi[base + 4];
            ahi[i][3] = Ahi[base + 8 * AKP + 4];
            alo[i][0] = Alo[base];
            alo[i][1] = Alo[base + 8 * AKP];
            alo[i][2] = Alo[base + 4];
            alo[i][3] = Alo[base + 8 * AKP + 4];
        }
        uint32_t bhi[NT][2], blo[NT][2];
#pragma unroll
        for (int j = 0; j < NT; j++) {
            int col = nbase + j * 8 + g;
            int b0 = (kb + t) * WKP + col;
            int b1 = (kb + 4 + t) * WKP + col;
            bhi[j][0] = Whi[b0];
            bhi[j][1] = Whi[b1];
            blo[j][0] = Wlo[b0];
            blo[j][1] = Wlo[b1];
        }
#pragma unroll
        for (int i = 0; i < 2; i++)
#pragma unroll
            for (int j = 0; j < NT; j++) {
                mma_bf16(acc[i][j], ahi[i], bhi[j]);
                mma_bf16(acc[i][j], ahi[i], blo[j]);
                mma_bf16(acc[i][j], alo[i], bhi[j]);
            }
    }

#pragma unroll
    for (int i = 0; i < 2; i++) {
        int r_lo = row0 + mbase + i * 16 + g;
        int r_hi = r_lo + 8;
        float s_lo = (r_lo < M) ? g_dinv[r_lo] : 0.f;
        float s_hi = (r_hi < M) ? g_dinv[r_hi] : 0.f;
#pragma unroll
        for (int j = 0; j < NT; j++) {
            int col = nbase + j * 8 + 2 * t;
            if (r_lo < M)
                *(float2*)&g_t[(size_t)r_lo * DOUT + col] =
                    make_float2(s_lo * acc[i][j][0], s_lo * acc[i][j][1]);
            if (r_hi < M)
                *(float2*)&g_t[(size_t)r_hi * DOUT + col] =
                    make_float2(s_hi * acc[i][j][2], s_hi * acc[i][j][3]);
        }
    }
}

// ================= Aggregation (warp per node), fused epilogue =================
// acc = t[i] + sum_s t[s];  res = dinv_i*acc + bias
// MODE 0: relu -> packed bf16 hi/lo (g_ahi/g_alo).  MODE 1: log_softmax -> out.
template<int DOUT, int MODE>
__global__ void k_agg(const float* __restrict__ bias, float* __restrict__ out, int n) {
    int w    = (blockIdx.x * blockDim.x + threadIdx.x) >> 5;
    int lane = threadIdx.x & 31;
    if (w >= n) return;
    constexpr int VF = DOUT / 32;

    float acc[VF];
    {
        const float* p = g_t + (size_t)w * DOUT + lane * VF;
        if (VF == 4) { float4 v = *(const float4*)p; acc[0]=v.x; acc[1]=v.y; acc[2]=v.z; acc[3]=v.w; }
        else         { float2 v = *(const float2*)p; acc[0]=v.x; acc[1]=v.y; }
    }

    int beg = g_rowptr[w], end = g_rowptr[w + 1];
    for (int jb = beg; jb < end; jb += 32) {
        int myj = jb + lane;
        int ms  = (myj < end) ? g_csr_src[myj] : 0;
        int cnt = min(32, end - jb);
        int k = 0;
        for (; k + 4 <= cnt; k += 4) {
            int s0 = __shfl_sync(0xffffffffu, ms, k);
            int s1 = __shfl_sync(0xffffffffu, ms, k + 1);
            int s2 = __shfl_sync(0xffffffffu, ms, k + 2);
            int s3 = __shfl_sync(0xffffffffu, ms, k + 3);
            if (VF == 4) {
                float4 v0 = *(const float4*)(g_t + (size_t)s0 * DOUT + lane * 4);
                float4 v1 = *(const float4*)(g_t + (size_t)s1 * DOUT + lane * 4);
                float4 v2 = *(const float4*)(g_t + (size_t)s2 * DOUT + lane * 4);
                float4 v3 = *(const float4*)(g_t + (size_t)s3 * DOUT + lane * 4);
                acc[0] += (v0.x + v1.x) + (v2.x + v3.x);
                acc[1] += (v0.y + v1.y) + (v2.y + v3.y);
                acc[2] += (v0.z + v1.z) + (v2.z + v3.z);
                acc[3] += (v0.w + v1.w) + (v2.w + v3.w);
            } else {
                float2 v0 = *(const float2*)(g_t + (size_t)s0 * DOUT + lane * 2);
                float2 v1 = *(const float2*)(g_t + (size_t)s1 * DOUT + lane * 2);
                float2 v2 = *(const float2*)(g_t + (size_t)s2 * DOUT + lane * 2);
                float2 v3 = *(const float2*)(g_t + (size_t)s3 * DOUT + lane * 2);
                acc[0] += (v0.x + v1.x) + (v2.x + v3.x);
                acc[1] += (v0.y + v1.y) + (v2.y + v3.y);
            }
        }
        for (; k < cnt; k++) {
            int s = __shfl_sync(0xffffffffu, ms, k);
            if (VF == 4) {
                float4 v = *(const float4*)(g_t + (size_t)s * DOUT + lane * 4);
                acc[0] += v.x; acc[1] += v.y; acc[2] += v.z; acc[3] += v.w;
            } else {
                float2 v = *(const float2*)(g_t + (size_t)s * DOUT + lane * 2);
                acc[0] += v.x; acc[1] += v.y;
            }
        }
    }

    float di = g_dinv[w];
    if (MODE == 0) {
        float4 bb = ((const float4*)bias)[lane];
        float rx = fmaxf(fmaf(di, acc[0], bb.x), 0.f);
        float ry = fmaxf(fmaf(di, acc[1], bb.y), 0.f);
        float rz = fmaxf(fmaf(di, acc[2], bb.z), 0.f);
        float rw = fmaxf(fmaf(di, acc[3], bb.w), 0.f);
        uint32_t h0, l0, h1, l1;
        pack_split(make_float2(rx, ry), h0, l0);
        pack_split(make_float2(rz, rw), h1, l1);
        *(uint2*)(g_ahi + (size_t)w * 64 + lane * 2) = make_uint2(h0, h1);
        *(uint2*)(g_alo + (size_t)w * 64 + lane * 2) = make_uint2(l0, l1);
    } else {
        float2 bb = ((const float2*)bias)[lane];
        float vx = fmaf(di, acc[0], bb.x);
        float vy = fmaf(di, acc[1], bb.y);
        float m = fmaxf(vx, vy);
#pragma unroll
        for (int o = 16; o; o >>= 1) m = fmaxf(m, __shfl_xor_sync(0xffffffffu, m, o));
        float sum = expf(vx - m) + expf(vy - m);
#pragma unroll
        for (int o = 16; o; o >>= 1) sum += __shfl_xor_sync(0xffffffffu, sum, o);
        float lse = m + logf(sum);
        *(float2*)(out + (size_t)w * 64 + lane * 2) = make_float2(vx - lse, vy - lse);
    }
}

// ================= launch =================
extern "C" void kernel_launch(void* const* d_in, const int* in_sizes, int n_in,
                              void* d_out, int out_size) {
    const float* x   = (const float*)d_in[0];
    const int*   ei  = (const int*)d_in[1];     // int32 (JAX x64 disabled)
    const float* W1  = (const float*)d_in[2];
    const float* b1  = (const float*)d_in[3];
    const float* W2  = (const float*)d_in[4];
    const float* b2  = (const float*)d_in[5];
    const float* W3  = (const float*)d_in[6];
    const float* b3  = (const float*)d_in[7];
    float* out = (float*)d_out;

    int n = in_sizes[0] / FIN;
    int e = in_sizes[1] / 2;
    const int* srcp = ei;
    const int* dstp = ei + e;

    const int smem1   = (64 * (FIN + 8) + 128 * (HH + 4)) * 4;          // ~100 KB
    const int smemp128 = (2 * 64 * 68 + 2 * 64 * (HH   + 8)) * 4;       // ~102 KB -> 2 CTA/SM
    const int smemp64  = (2 * 64 * 68 + 2 * 64 * (OUTC + 8)) * 4;       // ~70 KB  -> 3 CTA/SM
    cudaFuncSetAttribute(k_gemm1,          cudaFuncAttributeMaxDynamicSharedMemorySize, smem1);
    cudaFuncSetAttribute(k_gemm_pre<HH>,   cudaFuncAttributeMaxDynamicSharedMemorySize, smemp128);
    cudaFuncSetAttribute(k_gemm_pre<OUTC>, cudaFuncAttributeMaxDynamicSharedMemorySize, smemp64);

    int nb_scan = (n + 1023) >> 10;
    int gemm_blocks = (n + 63) / 64;
    int agg_blocks  = (int)(((long long)n * 32 + 255) / 256);

    // CSR build + dinv (launch #4 = profiled gemm1, which only needs dinv)
    k_zero <<<(n + 255) / 256, 256>>>(n);                  // 1
    k_count<<<(e + 255) / 256, 256>>>(dstp, e);            // 2
    k_scan1<<<nb_scan, 1024>>>(n);                         // 3 (dinv ready)
    k_gemm1<<<gemm_blocks, 256, smem1>>>(x, W1, n);        // 4 <-- profiled
    k_scan2<<<1, 128>>>(nb_scan, n);                       // 5
    k_scan3<<<(n + 255) / 256, 256>>>(n);                  // 6
    k_fill <<<(e + 255) / 256, 256>>>(srcp, dstp, e);      // 7

    // layer 1 aggregate -> packed bf16 activations
    k_agg<HH, 0><<<agg_blocks, 256>>>(b1, nullptr, n);
    // layer 2
    k_split_w<HH><<<(64 * HH + 255) / 256, 256>>>(W2);
    k_gemm_pre<HH><<<gemm_blocks, 256, smemp128>>>(n);
    k_agg<HH, 0><<<agg_blocks, 256>>>(b2, nullptr, n);
    // layer 3
    k_split_w<OUTC><<<(64 * OUTC + 255) / 256, 256>>>(W3);
    k_gemm_pre<OUTC><<<gemm_blocks, 256, smemp64>>>(n);
    k_agg<OUTC, 1><<<agg_blocks, 256>>>(b3, out, n);
}

// round 14
// speedup vs baseline: 1.1943x; 1.0425x over previous
#include <cuda_runtime.h>
#include <cstdint>

#define NN   100000
#define EE   1600000
#define FIN  128
#define HH   128
#define OUTC 64

// ---------------- scratch (no allocation allowed) ----------------
__device__ __align__(16) int   g_cnt[NN];
__device__ __align__(16) int   g_rowptr[NN + 1];
__device__ __align__(16) int   g_cursor[NN];
__device__ __align__(16) int   g_bsum[256];
__device__ __align__(16) float g_dinv[NN];
__device__ __align__(16) int   g_csr_src[EE];
__device__ __align__(16) float g_t[(size_t)NN * HH];          // GEMM output (dinv-scaled)
__device__ __align__(16) uint32_t g_ahi[(size_t)NN * 64];     // activation hi (bf16x2, kp-major)
__device__ __align__(16) uint32_t g_alo[(size_t)NN * 64];     // activation lo
__device__ __align__(16) uint32_t g_whi[64 * HH];             // W pre-split hi [kp][n]
__device__ __align__(16) uint32_t g_wlo[64 * HH];             // W pre-split lo

// ================= bf16-split helpers =================
__device__ __forceinline__ void pack_split(float2 v, uint32_t& hi, uint32_t& lo) {
    asm("cvt.rn.bf16x2.f32 %0, %1, %2;" : "=r"(hi) : "f"(v.y), "f"(v.x));
    float h0 = __uint_as_float(hi << 16);
    float h1 = __uint_as_float(hi & 0xFFFF0000u);
    float l0 = v.x - h0;
    float l1 = v.y - h1;
    asm("cvt.rn.bf16x2.f32 %0, %1, %2;" : "=r"(lo) : "f"(l1), "f"(l0));
}
__device__ __forceinline__ void mma_bf16(float c[4], const uint32_t a[4], const uint32_t b[2]) {
    asm volatile(
        "mma.sync.aligned.m16n8k16.row.col.f32.bf16.bf16.f32 "
        "{%0,%1,%2,%3}, {%4,%5,%6,%7}, {%8,%9}, {%0,%1,%2,%3};"
        : "+f"(c[0]), "+f"(c[1]), "+f"(c[2]), "+f"(c[3])
        : "r"(a[0]), "r"(a[1]), "r"(a[2]), "r"(a[3]), "r"(b[0]), "r"(b[1]));
}

// ================= CSR construction =================
__global__ void k_zero(int n) {
    int i = blockIdx.x * blockDim.x + threadIdx.x;
    if (i < n) g_cnt[i] = 0;
}
__global__ void k_count(const int* __restrict__ dst, int e) {
    int i = blockIdx.x * blockDim.x + threadIdx.x;
    if (i < e) atomicAdd(&g_cnt[dst[i]], 1);
}
// dinv from counts + pre-split W1 (fused so gemm1 can run before the scans)
__global__ void k_prep(const float* __restrict__ W1, int n) {
    int i = blockIdx.x * blockDim.x + threadIdx.x;
    if (i < n) g_dinv[i] = rsqrtf(1.0f + (float)g_cnt[i]);
    if (i < 64 * HH) {
        int kp = i / HH;
        int nn = i % HH;
        float2 v = make_float2(W1[(2 * kp) * HH + nn], W1[(2 * kp + 1) * HH + nn]);
        uint32_t hi, lo;
        pack_split(v, hi, lo);
        g_whi[i] = hi;
        g_wlo[i] = lo;
    }
}
__global__ void k_scan1(int n) {
    __shared__ int sh[1024];
    int tid = threadIdx.x;
    int i = blockIdx.x * 1024 + tid;
    int v = (i < n) ? g_cnt[i] : 0;
    sh[tid] = v;
    __syncthreads();
#pragma unroll
    for (int off = 1; off < 1024; off <<= 1) {
        int t = (tid >= off) ? sh[tid - off] : 0;
        __syncthreads();
        sh[tid] += t;
        __syncthreads();
    }
    if (i < n) g_rowptr[i] = sh[tid] - v;
    if (tid == 1023) g_bsum[blockIdx.x] = sh[1023];
}
__global__ void k_scan2(int nb, int n) {
    __shared__ int sh[128];
    int tid = threadIdx.x;
    int v = (tid < nb) ? g_bsum[tid] : 0;
    sh[tid] = v;
    __syncthreads();
#pragma unroll
    for (int off = 1; off < 128; off <<= 1) {
        int t = (tid >= off) ? sh[tid - off] : 0;
        __syncthreads();
        sh[tid] += t;
        __syncthreads();
    }
    if (tid < nb) g_bsum[tid] = sh[tid] - v;
    if (tid == 127) g_rowptr[n] = sh[127];
}
__global__ void k_scan3(int n) {
    int i = blockIdx.x * blockDim.x + threadIdx.x;
    if (i >= n) return;
    int v = g_rowptr[i] + g_bsum[i >> 10];
    g_rowptr[i] = v;
    g_cursor[i] = v;
}
__global__ void k_fill(const int* __restrict__ src, const int* __restrict__ dst, int e) {
    int i = blockIdx.x * blockDim.x + threadIdx.x;
    if (i >= e) return;
    int d = dst[i];
    int pos = atomicAdd(&g_cursor[d], 1);
    g_csr_src[pos] = src[i];
}

// ================= W pre-split (layers 2/3) =================
template<int DOUT>
__global__ void k_split_w(const float* __restrict__ W) {
    int i = blockIdx.x * blockDim.x + threadIdx.x;
    if (i >= 64 * DOUT) return;
    int kp = i / DOUT;
    int nn = i % DOUT;
    float2 v = make_float2(W[(2 * kp) * DOUT + nn], W[(2 * kp + 1) * DOUT + nn]);
    uint32_t hi, lo;
    pack_split(v, hi, lo);
    g_whi[i] = hi;
    g_wlo[i] = lo;
}

// ======== GEMM: pre-split bf16 operands, PURE LDS+MMA mainloop ====================
// FROM_X=1: A staged from f32 x (split once during staging).
// FROM_X=0: A staged from packed g_ahi/g_alo. W always from g_whi/g_wlo.
// g_t[M,DOUT] = dinv[m] * (A @ W). CTA tile 64 x DOUT, 256 threads (2m x 4n warps).
template<int DOUT, int FROM_X>
__global__ __launch_bounds__(256, 2)
void k_gemm_pre(const float* __restrict__ Ax, int M) {
    constexpr int KP  = 64;
    constexpr int AKP = KP + 4;        // 68: frag banks 4g+t -> conflict-free
    constexpr int WKP = DOUT + 8;      // frag banks 8t+g -> conflict-free
    constexpr int NT  = DOUT / 32;

    extern __shared__ uint32_t smu[];
    uint32_t* Ahi = smu;                          // [64][AKP]
    uint32_t* Alo = Ahi + 64 * AKP;
    uint32_t* Whi = Alo + 64 * AKP;               // [KP][WKP]
    uint32_t* Wlo = Whi + KP * WKP;

    int tid  = threadIdx.x;
    int row0 = blockIdx.x * 64;

    // stage W (uint4 copies of pre-split data)
    for (int i = tid; i < KP * (DOUT / 4); i += 256) {
        int kp = i / (DOUT / 4);
        int n4 = i % (DOUT / 4);
        uint4 h = ((const uint4*)g_whi)[(size_t)kp * (DOUT / 4) + n4];
        uint4 l = ((const uint4*)g_wlo)[(size_t)kp * (DOUT / 4) + n4];
        *(uint4*)(Whi + kp * WKP + n4 * 4) = h;
        *(uint4*)(Wlo + kp * WKP + n4 * 4) = l;
    }
    // stage A
    for (int i = tid; i < 64 * 32; i += 256) {
        int r = i >> 5;
        int c = i & 31;                 // 2 kp per c
        int gr = row0 + r;
        uint2 h = make_uint2(0u, 0u), l = make_uint2(0u, 0u);
        if (FROM_X) {
            float4 v = make_float4(0.f, 0.f, 0.f, 0.f);
            if (gr < M) v = ((const float4*)Ax)[(size_t)gr * 32 + c];
            pack_split(make_float2(v.x, v.y), h.x, l.x);
            pack_split(make_float2(v.z, v.w), h.y, l.y);
        } else if (gr < M) {
            h = ((const uint2*)(g_ahi + (size_t)gr * 64))[c];
            l = ((const uint2*)(g_alo + (size_t)gr * 64))[c];
        }
        *(uint2*)(Ahi + r * AKP + c * 2) = h;
        *(uint2*)(Alo + r * AKP + c * 2) = l;
    }
    __syncthreads();

    int warp = tid >> 5, lane = tid & 31;
    int wm = warp & 1;
    int wn = warp >> 1;
    int g  = lane >> 2;
    int t  = lane & 3;
    int mbase = wm * 32;
    int nbase = wn * (DOUT / 4);

    float acc[2][NT][4];
#pragma unroll
    for (int i = 0; i < 2; i++)
#pragma unroll
        for (int j = 0; j < NT; j++)
#pragma unroll
            for (int q = 0; q < 4; q++) acc[i][j][q] = 0.f;

#pragma unroll 2
    for (int kb = 0; kb < KP; kb += 8) {          // k16 per step
        uint32_t ahi[2][4], alo[2][4];
#pragma unroll
        for (int i = 0; i < 2; i++) {
            int base = (mbase + i * 16 + g) * AKP + kb + t;
            ahi[i][0] = Ahi[base];
            ahi[i][1] = Ahi[base + 8 * AKP];
            ahi[i][2] = Ahi[base + 4];
            ahi[i][3] = Ahi[base + 8 * AKP + 4];
            alo[i][0] = Alo[base];
            alo[i][1] = Alo[base + 8 * AKP];
            alo[i][2] = Alo[base + 4];
            alo[i][3] = Alo[base + 8 * AKP + 4];
        }
        uint32_t bhi[NT][2], blo[NT][2];
#pragma unroll
        for (int j = 0; j < NT; j++) {
            int col = nbase + j * 8 + g;
            int b0 = (kb + t) * WKP + col;
            int b1 = (kb + 4 + t) * WKP + col;
            bhi[j][0] = Whi[b0];
            bhi[j][1] = Whi[b1];
            blo[j][0] = Wlo[b0];
            blo[j][1] = Wlo[b1];
        }
#pragma unroll
        for (int i = 0; i < 2; i++)
#pragma unroll
            for (int j = 0; j < NT; j++) {
                mma_bf16(acc[i][j], ahi[i], bhi[j]);
                mma_bf16(acc[i][j], ahi[i], blo[j]);
                mma_bf16(acc[i][j], alo[i], bhi[j]);
            }
    }

#pragma unroll
    for (int i = 0; i < 2; i++) {
        int r_lo = row0 + mbase + i * 16 + g;
        int r_hi = r_lo + 8;
        float s_lo = (r_lo < M) ? g_dinv[r_lo] : 0.f;
        float s_hi = (r_hi < M) ? g_dinv[r_hi] : 0.f;
#pragma unroll
        for (int j = 0; j < NT; j++) {
            int col = nbase + j * 8 + 2 * t;
            if (r_lo < M)
                *(float2*)&g_t[(size_t)r_lo * DOUT + col] =
                    make_float2(s_lo * acc[i][j][0], s_lo * acc[i][j][1]);
            if (r_hi < M)
                *(float2*)&g_t[(size_t)r_hi * DOUT + col] =
                    make_float2(s_hi * acc[i][j][2], s_hi * acc[i][j][3]);
        }
    }
}

// ================= Aggregation (warp per node), fused epilogue =================
// acc = t[i] + sum_s t[s];  res = dinv_i*acc + bias
// MODE 0: relu -> packed bf16 hi/lo (g_ahi/g_alo).  MODE 1: log_softmax -> out.
template<int DOUT, int MODE>
__global__ void k_agg(const float* __restrict__ bias, float* __restrict__ out, int n) {
    int w    = (blockIdx.x * blockDim.x + threadIdx.x) >> 5;
    int lane = threadIdx.x & 31;
    if (w >= n) return;
    constexpr int VF = DOUT / 32;

    float acc[VF];
    {
        const float* p = g_t + (size_t)w * DOUT + lane * VF;
        if (VF == 4) { float4 v = *(const float4*)p; acc[0]=v.x; acc[1]=v.y; acc[2]=v.z; acc[3]=v.w; }
        else         { float2 v = *(const float2*)p; acc[0]=v.x; acc[1]=v.y; }
    }

    int beg = g_rowptr[w], end = g_rowptr[w + 1];
    for (int jb = beg; jb < end; jb += 32) {
        int myj = jb + lane;
        int ms  = (myj < end) ? g_csr_src[myj] : 0;
        int cnt = min(32, end - jb);
        int k = 0;
        for (; k + 4 <= cnt; k += 4) {
            int s0 = __shfl_sync(0xffffffffu, ms, k);
            int s1 = __shfl_sync(0xffffffffu, ms, k + 1);
            int s2 = __shfl_sync(0xffffffffu, ms, k + 2);
            int s3 = __shfl_sync(0xffffffffu, ms, k + 3);
            if (VF == 4) {
                float4 v0 = *(const float4*)(g_t + (size_t)s0 * DOUT + lane * 4);
                float4 v1 = *(const float4*)(g_t + (size_t)s1 * DOUT + lane * 4);
                float4 v2 = *(const float4*)(g_t + (size_t)s2 * DOUT + lane * 4);
                float4 v3 = *(const float4*)(g_t + (size_t)s3 * DOUT + lane * 4);
                acc[0] += (v0.x + v1.x) + (v2.x + v3.x);
                acc[1] += (v0.y + v1.y) + (v2.y + v3.y);
                acc[2] += (v0.z + v1.z) + (v2.z + v3.z);
                acc[3] += (v0.w + v1.w) + (v2.w + v3.w);
            } else {
                float2 v0 = *(const float2*)(g_t + (size_t)s0 * DOUT + lane * 2);
                float2 v1 = *(const float2*)(g_t + (size_t)s1 * DOUT + lane * 2);
                float2 v2 = *(const float2*)(g_t + (size_t)s2 * DOUT + lane * 2);
                float2 v3 = *(const float2*)(g_t + (size_t)s3 * DOUT + lane * 2);
                acc[0] += (v0.x + v1.x) + (v2.x + v3.x);
                acc[1] += (v0.y + v1.y) + (v2.y + v3.y);
            }
        }
        for (; k < cnt; k++) {
            int s = __shfl_sync(0xffffffffu, ms, k);
            if (VF == 4) {
                float4 v = *(const float4*)(g_t + (size_t)s * DOUT + lane * 4);
                acc[0] += v.x; acc[1] += v.y; acc[2] += v.z; acc[3] += v.w;
            } else {
                float2 v = *(const float2*)(g_t + (size_t)s * DOUT + lane * 2);
                acc[0] += v.x; acc[1] += v.y;
            }
        }
    }

    float di = g_dinv[w];
    if (MODE == 0) {
        float4 bb = ((const float4*)bias)[lane];
        float rx = fmaxf(fmaf(di, acc[0], bb.x), 0.f);
        float ry = fmaxf(fmaf(di, acc[1], bb.y), 0.f);
        float rz = fmaxf(fmaf(di, acc[2], bb.z), 0.f);
        float rw = fmaxf(fmaf(di, acc[3], bb.w), 0.f);
        uint32_t h0, l0, h1, l1;
        pack_split(make_float2(rx, ry), h0, l0);
        pack_split(make_float2(rz, rw), h1, l1);
        *(uint2*)(g_ahi + (size_t)w * 64 + lane * 2) = make_uint2(h0, h1);
        *(uint2*)(g_alo + (size_t)w * 64 + lane * 2) = make_uint2(l0, l1);
    } else {
        float2 bb = ((const float2*)bias)[lane];
        float vx = fmaf(di, acc[0], bb.x);
        float vy = fmaf(di, acc[1], bb.y);
        float m = fmaxf(vx, vy);
#pragma unroll
        for (int o = 16; o; o >>= 1) m = fmaxf(m, __shfl_xor_sync(0xffffffffu, m, o));
        float sum = expf(vx - m) + expf(vy - m);
#pragma unroll
        for (int o = 16; o; o >>= 1) sum += __shfl_xor_sync(0xffffffffu, sum, o);
        float lse = m + logf(sum);
        *(float2*)(out + (size_t)w * 64 + lane * 2) = make_float2(vx - lse, vy - lse);
    }
}

// ================= launch =================
extern "C" void kernel_launch(void* const* d_in, const int* in_sizes, int n_in,
                              void* d_out, int out_size) {
    const float* x   = (const float*)d_in[0];
    const int*   ei  = (const int*)d_in[1];     // int32 (JAX x64 disabled)
    const float* W1  = (const float*)d_in[2];
    const float* b1  = (const float*)d_in[3];
    const float* W2  = (const float*)d_in[4];
    const float* b2  = (const float*)d_in[5];
    const float* W3  = (const float*)d_in[6];
    const float* b3  = (const float*)d_in[7];
    float* out = (float*)d_out;

    int n = in_sizes[0] / FIN;
    int e = in_sizes[1] / 2;
    const int* srcp = ei;
    const int* dstp = ei + e;

    const int smemp128 = (2 * 64 * 68 + 2 * 64 * (HH   + 8)) * 4;   // ~102 KB -> 2 CTA/SM
    const int smemp64  = (2 * 64 * 68 + 2 * 64 * (OUTC + 8)) * 4;   // ~70 KB  -> 3 CTA/SM
    cudaFuncSetAttribute((const void*)k_gemm_pre<HH, 1>,
                         cudaFuncAttributeMaxDynamicSharedMemorySize, smemp128);
    cudaFuncSetAttribute((const void*)k_gemm_pre<HH, 0>,
                         cudaFuncAttributeMaxDynamicSharedMemorySize, smemp128);
    cudaFuncSetAttribute((const void*)k_gemm_pre<OUTC, 0>,
                         cudaFuncAttributeMaxDynamicSharedMemorySize, smemp64);

    int nb_scan = (n + 1023) >> 10;
    int gemm_blocks = (n + 63) / 64;
    int agg_blocks  = (int)(((long long)n * 32 + 255) / 256);

    // launch #4 = profiled gemm1; its deps (counts->dinv, W1 split) land in 1-3.
    k_zero <<<(n + 255) / 256, 256>>>(n);                          // 1
    k_count<<<(e + 255) / 256, 256>>>(dstp, e);                    // 2
    k_prep <<<(n + 255) / 256, 256>>>(W1, n);                      // 3 (dinv + split W1)
    k_gemm_pre<HH, 1><<<gemm_blocks, 256, smemp128>>>(x, n);       // 4 <-- profiled
    k_scan1<<<nb_scan, 1024>>>(n);                                 // 5
    k_scan2<<<1, 128>>>(nb_scan, n);                               // 6
    k_scan3<<<(n + 255) / 256, 256>>>(n);                          // 7
    k_fill <<<(e + 255) / 256, 256>>>(srcp, dstp, e);              // 8

    // layer 1 aggregate -> packed bf16 activations
    k_agg<HH, 0><<<agg_blocks, 256>>>(b1, nullptr, n);
    // layer 2
    k_split_w<HH><<<(64 * HH + 255) / 256, 256>>>(W2);
    k_gemm_pre<HH, 0><<<gemm_blocks, 256, smemp128>>>(nullptr, n);
    k_agg<HH, 0><<<agg_blocks, 256>>>(b2, nullptr, n);
    // layer 3
    k_split_w<OUTC><<<(64 * OUTC + 255) / 256, 256>>>(W3);
    k_gemm_pre<OUTC, 0><<<gemm_blocks, 256, smemp64>>>(nullptr, n);
    k_agg<OUTC, 1><<<agg_blocks, 256>>>(b3, out, n);
}

// round 15
// speedup vs baseline: 1.2241x; 1.0250x over previous
#include <cuda_runtime.h>
#include <cstdint>

#define NN   100000
#define EE   1600000
#define FIN  128
#define HH   128
#define OUTC 64

// ---------------- scratch (no allocation allowed) ----------------
__device__ __align__(16) int   g_cnt[NN];
__device__ __align__(16) int   g_rowptr[NN + 1];
__device__ __align__(16) int   g_cursor[NN];
__device__ __align__(16) int   g_bsum[256];
__device__ __align__(16) float g_dinv[NN];
__device__ __align__(16) int   g_csr_src[EE];
__device__ __align__(16) float g_t[(size_t)NN * HH];          // GEMM output (dinv-scaled)
__device__ __align__(16) uint32_t g_ahi[(size_t)NN * 64];     // activation hi (bf16x2, kp-major)
__device__ __align__(16) uint32_t g_alo[(size_t)NN * 64];     // activation lo
__device__ __align__(16) uint32_t g_w1hi[64 * HH],   g_w1lo[64 * HH];
__device__ __align__(16) uint32_t g_w2hi[64 * HH],   g_w2lo[64 * HH];
__device__ __align__(16) uint32_t g_w3hi[64 * OUTC], g_w3lo[64 * OUTC];

// ================= bf16-split helpers =================
__device__ __forceinline__ void pack_split(float2 v, uint32_t& hi, uint32_t& lo) {
    asm("cvt.rn.bf16x2.f32 %0, %1, %2;" : "=r"(hi) : "f"(v.y), "f"(v.x));
    float h0 = __uint_as_float(hi << 16);
    float h1 = __uint_as_float(hi & 0xFFFF0000u);
    float l0 = v.x - h0;
    float l1 = v.y - h1;
    asm("cvt.rn.bf16x2.f32 %0, %1, %2;" : "=r"(lo) : "f"(l1), "f"(l0));
}
__device__ __forceinline__ void mma_bf16(float c[4], const uint32_t a[4], const uint32_t b[2]) {
    asm volatile(
        "mma.sync.aligned.m16n8k16.row.col.f32.bf16.bf16.f32 "
        "{%0,%1,%2,%3}, {%4,%5,%6,%7}, {%8,%9}, {%0,%1,%2,%3};"
        : "+f"(c[0]), "+f"(c[1]), "+f"(c[2]), "+f"(c[3])
        : "r"(a[0]), "r"(a[1]), "r"(a[2]), "r"(a[3]), "r"(b[0]), "r"(b[1]));
}

// ================= CSR construction =================
__global__ void k_zero(int n) {
    int i = blockIdx.x * blockDim.x + threadIdx.x;
    if (i < n) g_cnt[i] = 0;
}
__global__ void k_count(const int* __restrict__ dst, int e) {
    int i = blockIdx.x * blockDim.x + threadIdx.x;
    if (i < e) atomicAdd(&g_cnt[dst[i]], 1);
}
// dinv from counts + pre-split ALL weight matrices (one pass)
__global__ void k_prep(const float* __restrict__ W1, const float* __restrict__ W2,
                       const float* __restrict__ W3, int n) {
    int i = blockIdx.x * blockDim.x + threadIdx.x;
    if (i < n) g_dinv[i] = rsqrtf(1.0f + (float)g_cnt[i]);
    if (i < 64 * HH) {
        int kp = i / HH, nn = i % HH;
        uint32_t hi, lo;
        pack_split(make_float2(W1[(2 * kp) * HH + nn], W1[(2 * kp + 1) * HH + nn]), hi, lo);
        g_w1hi[i] = hi; g_w1lo[i] = lo;
        pack_split(make_float2(W2[(2 * kp) * HH + nn], W2[(2 * kp + 1) * HH + nn]), hi, lo);
        g_w2hi[i] = hi; g_w2lo[i] = lo;
    }
    if (i < 64 * OUTC) {
        int kp = i / OUTC, nn = i % OUTC;
        uint32_t hi, lo;
        pack_split(make_float2(W3[(2 * kp) * OUTC + nn], W3[(2 * kp + 1) * OUTC + nn]), hi, lo);
        g_w3hi[i] = hi; g_w3lo[i] = lo;
    }
}
__global__ void k_scan1(int n) {
    __shared__ int sh[1024];
    int tid = threadIdx.x;
    int i = blockIdx.x * 1024 + tid;
    int v = (i < n) ? g_cnt[i] : 0;
    sh[tid] = v;
    __syncthreads();
#pragma unroll
    for (int off = 1; off < 1024; off <<= 1) {
        int t = (tid >= off) ? sh[tid - off] : 0;
        __syncthreads();
        sh[tid] += t;
        __syncthreads();
    }
    if (i < n) g_rowptr[i] = sh[tid] - v;
    if (tid == 1023) g_bsum[blockIdx.x] = sh[1023];
}
__global__ void k_scan2(int nb, int n) {
    __shared__ int sh[128];
    int tid = threadIdx.x;
    int v = (tid < nb) ? g_bsum[tid] : 0;
    sh[tid] = v;
    __syncthreads();
#pragma unroll
    for (int off = 1; off < 128; off <<= 1) {
        int t = (tid >= off) ? sh[tid - off] : 0;
        __syncthreads();
        sh[tid] += t;
        __syncthreads();
    }
    if (tid < nb) g_bsum[tid] = sh[tid] - v;
    if (tid == 127) g_rowptr[n] = sh[127];
}
__global__ void k_scan3(int n) {
    int i = blockIdx.x * blockDim.x + threadIdx.x;
    if (i >= n) return;
    int v = g_rowptr[i] + g_bsum[i >> 10];
    g_rowptr[i] = v;
    g_cursor[i] = v;
}
__global__ void k_fill(const int* __restrict__ src, const int* __restrict__ dst, int e) {
    int i = blockIdx.x * blockDim.x + threadIdx.x;
    if (i >= e) return;
    int d = dst[i];
    int pos = atomicAdd(&g_cursor[d], 1);
    g_csr_src[pos] = src[i];
}

// ======== GEMM: pre-split bf16 operands, PURE LDS+MMA mainloop ====================
// FROM_X=1: A staged from f32 x (split during staging). FROM_X=0: from g_ahi/g_alo.
// LAYER selects the pre-split weight buffers.
// g_t[M,DOUT] = dinv[m] * (A @ W). CTA tile 64 x DOUT, 256 threads (2m x 4n warps).
template<int DOUT, int FROM_X, int LAYER>
__global__ __launch_bounds__(256, 2)
void k_gemm_pre(const float* __restrict__ Ax, int M) {
    constexpr int KP  = 64;
    constexpr int AKP = KP + 4;        // 68: frag banks 4g+t -> conflict-free
    constexpr int WKP = DOUT + 8;      // frag banks 8t+g -> conflict-free
    constexpr int NT  = DOUT / 32;

    const uint32_t* Wh = (LAYER == 1) ? g_w1hi : (LAYER == 2) ? g_w2hi : g_w3hi;
    const uint32_t* Wl = (LAYER == 1) ? g_w1lo : (LAYER == 2) ? g_w2lo : g_w3lo;

    extern __shared__ uint32_t smu[];
    uint32_t* Ahi = smu;                          // [64][AKP]
    uint32_t* Alo = Ahi + 64 * AKP;
    uint32_t* Whi = Alo + 64 * AKP;               // [KP][WKP]
    uint32_t* Wlo = Whi + KP * WKP;

    int tid  = threadIdx.x;
    int row0 = blockIdx.x * 64;

    for (int i = tid; i < KP * (DOUT / 4); i += 256) {
        int kp = i / (DOUT / 4);
        int n4 = i % (DOUT / 4);
        uint4 h = ((const uint4*)Wh)[(size_t)kp * (DOUT / 4) + n4];
        uint4 l = ((const uint4*)Wl)[(size_t)kp * (DOUT / 4) + n4];
        *(uint4*)(Whi + kp * WKP + n4 * 4) = h;
        *(uint4*)(Wlo + kp * WKP + n4 * 4) = l;
    }
    for (int i = tid; i < 64 * 32; i += 256) {
        int r = i >> 5;
        int c = i & 31;
        int gr = row0 + r;
        uint2 h = make_uint2(0u, 0u), l = make_uint2(0u, 0u);
        if (FROM_X) {
            float4 v = make_float4(0.f, 0.f, 0.f, 0.f);
            if (gr < M) v = ((const float4*)Ax)[(size_t)gr * 32 + c];
            pack_split(make_float2(v.x, v.y), h.x, l.x);
            pack_split(make_float2(v.z, v.w), h.y, l.y);
        } else if (gr < M) {
            h = ((const uint2*)(g_ahi + (size_t)gr * 64))[c];
            l = ((const uint2*)(g_alo + (size_t)gr * 64))[c];
        }
        *(uint2*)(Ahi + r * AKP + c * 2) = h;
        *(uint2*)(Alo + r * AKP + c * 2) = l;
    }
    __syncthreads();

    int warp = tid >> 5, lane = tid & 31;
    int wm = warp & 1;
    int wn = warp >> 1;
    int g  = lane >> 2;
    int t  = lane & 3;
    int mbase = wm * 32;
    int nbase = wn * (DOUT / 4);

    float acc[2][NT][4];
#pragma unroll
    for (int i = 0; i < 2; i++)
#pragma unroll
        for (int j = 0; j < NT; j++)
#pragma unroll
            for (int q = 0; q < 4; q++) acc[i][j][q] = 0.f;

#pragma unroll 2
    for (int kb = 0; kb < KP; kb += 8) {
        uint32_t ahi[2][4], alo[2][4];
#pragma unroll
        for (int i = 0; i < 2; i++) {
            int base = (mbase + i * 16 + g) * AKP + kb + t;
            ahi[i][0] = Ahi[base];
            ahi[i][1] = Ahi[base + 8 * AKP];
            ahi[i][2] = Ahi[base + 4];
            ahi[i][3] = Ahi[base + 8 * AKP + 4];
            alo[i][0] = Alo[base];
            alo[i][1] = Alo[base + 8 * AKP];
            alo[i][2] = Alo[base + 4];
            alo[i][3] = Alo[base + 8 * AKP + 4];
        }
        uint32_t bhi[NT][2], blo[NT][2];
#pragma unroll
        for (int j = 0; j < NT; j++) {
            int col = nbase + j * 8 + g;
            int b0 = (kb + t) * WKP + col;
            int b1 = (kb + 4 + t) * WKP + col;
            bhi[j][0] = Whi[b0];
            bhi[j][1] = Whi[b1];
            blo[j][0] = Wlo[b0];
            blo[j][1] = Wlo[b1];
        }
#pragma unroll
        for (int i = 0; i < 2; i++)
#pragma unroll
            for (int j = 0; j < NT; j++) {
                mma_bf16(acc[i][j], ahi[i], bhi[j]);
                mma_bf16(acc[i][j], ahi[i], blo[j]);
                mma_bf16(acc[i][j], alo[i], bhi[j]);
            }
    }

#pragma unroll
    for (int i = 0; i < 2; i++) {
        int r_lo = row0 + mbase + i * 16 + g;
        int r_hi = r_lo + 8;
        float s_lo = (r_lo < M) ? g_dinv[r_lo] : 0.f;
        float s_hi = (r_hi < M) ? g_dinv[r_hi] : 0.f;
#pragma unroll
        for (int j = 0; j < NT; j++) {
            int col = nbase + j * 8 + 2 * t;
            if (r_lo < M)
                *(float2*)&g_t[(size_t)r_lo * DOUT + col] =
                    make_float2(s_lo * acc[i][j][0], s_lo * acc[i][j][1]);
            if (r_hi < M)
                *(float2*)&g_t[(size_t)r_hi * DOUT + col] =
                    make_float2(s_hi * acc[i][j][2], s_hi * acc[i][j][3]);
        }
    }
}

// ================= Aggregation (warp per node), fused epilogue =================
template<int DOUT, int MODE>
__global__ void k_agg(const float* __restrict__ bias, float* __restrict__ out, int n) {
    int w    = (blockIdx.x * blockDim.x + threadIdx.x) >> 5;
    int lane = threadIdx.x & 31;
    if (w >= n) return;
    constexpr int VF = DOUT / 32;

    float acc[VF];
    {
        const float* p = g_t + (size_t)w * DOUT + lane * VF;
        if (VF == 4) { float4 v = *(const float4*)p; acc[0]=v.x; acc[1]=v.y; acc[2]=v.z; acc[3]=v.w; }
        else         { float2 v = *(const float2*)p; acc[0]=v.x; acc[1]=v.y; }
    }

    int beg = g_rowptr[w], end = g_rowptr[w + 1];
    for (int jb = beg; jb < end; jb += 32) {
        int myj = jb + lane;
        int ms  = (myj < end) ? g_csr_src[myj] : 0;
        int cnt = min(32, end - jb);
        int k = 0;
        for (; k + 4 <= cnt; k += 4) {
            int s0 = __shfl_sync(0xffffffffu, ms, k);
            int s1 = __shfl_sync(0xffffffffu, ms, k + 1);
            int s2 = __shfl_sync(0xffffffffu, ms, k + 2);
            int s3 = __shfl_sync(0xffffffffu, ms, k + 3);
            if (VF == 4) {
                float4 v0 = *(const float4*)(g_t + (size_t)s0 * DOUT + lane * 4);
                float4 v1 = *(const float4*)(g_t + (size_t)s1 * DOUT + lane * 4);
                float4 v2 = *(const float4*)(g_t + (size_t)s2 * DOUT + lane * 4);
                float4 v3 = *(const float4*)(g_t + (size_t)s3 * DOUT + lane * 4);
                acc[0] += (v0.x + v1.x) + (v2.x + v3.x);
                acc[1] += (v0.y + v1.y) + (v2.y + v3.y);
                acc[2] += (v0.z + v1.z) + (v2.z + v3.z);
                acc[3] += (v0.w + v1.w) + (v2.w + v3.w);
            } else {
                float2 v0 = *(const float2*)(g_t + (size_t)s0 * DOUT + lane * 2);
                float2 v1 = *(const float2*)(g_t + (size_t)s1 * DOUT + lane * 2);
                float2 v2 = *(const float2*)(g_t + (size_t)s2 * DOUT + lane * 2);
                float2 v3 = *(const float2*)(g_t + (size_t)s3 * DOUT + lane * 2);
                acc[0] += (v0.x + v1.x) + (v2.x + v3.x);
                acc[1] += (v0.y + v1.y) + (v2.y + v3.y);
            }
        }
        for (; k < cnt; k++) {
            int s = __shfl_sync(0xffffffffu, ms, k);
            if (VF == 4) {
                float4 v = *(const float4*)(g_t + (size_t)s * DOUT + lane * 4);
                acc[0] += v.x; acc[1] += v.y; acc[2] += v.z; acc[3] += v.w;
            } else {
                float2 v = *(const float2*)(g_t + (size_t)s * DOUT + lane * 2);
                acc[0] += v.x; acc[1] += v.y;
            }
        }
    }

    float di = g_dinv[w];
    if (MODE == 0) {
        float4 bb = ((const float4*)bias)[lane];
        float rx = fmaxf(fmaf(di, acc[0], bb.x), 0.f);
        float ry = fmaxf(fmaf(di, acc[1], bb.y), 0.f);
        float rz = fmaxf(fmaf(di, acc[2], bb.z), 0.f);
        float rw = fmaxf(fmaf(di, acc[3], bb.w), 0.f);
        uint32_t h0, l0, h1, l1;
        pack_split(make_float2(rx, ry), h0, l0);
        pack_split(make_float2(rz, rw), h1, l1);
        *(uint2*)(g_ahi + (size_t)w * 64 + lane * 2) = make_uint2(h0, h1);
        *(uint2*)(g_alo + (size_t)w * 64 + lane * 2) = make_uint2(l0, l1);
    } else {
        float2 bb = ((const float2*)bias)[lane];
        float vx = fmaf(di, acc[0], bb.x);
        float vy = fmaf(di, acc[1], bb.y);
        float m = fmaxf(vx, vy);
#pragma unroll
        for (int o = 16; o; o >>= 1) m = fmaxf(m, __shfl_xor_sync(0xffffffffu, m, o));
        float sum = expf(vx - m) + expf(vy - m);
#pragma unroll
        for (int o = 16; o; o >>= 1) sum += __shfl_xor_sync(0xffffffffu, sum, o);
        float lse = m + logf(sum);
        *(float2*)(out + (size_t)w * 64 + lane * 2) = make_float2(vx - lse, vy - lse);
    }
}

// ================= launch =================
extern "C" void kernel_launch(void* const* d_in, const int* in_sizes, int n_in,
                              void* d_out, int out_size) {
    const float* x   = (const float*)d_in[0];
    const int*   ei  = (const int*)d_in[1];     // int32 (JAX x64 disabled)
    const float* W1  = (const float*)d_in[2];
    const float* b1  = (const float*)d_in[3];
    const float* W2  = (const float*)d_in[4];
    const float* b2  = (const float*)d_in[5];
    const float* W3  = (const float*)d_in[6];
    const float* b3  = (const float*)d_in[7];
    float* out = (float*)d_out;

    int n = in_sizes[0] / FIN;
    int e = in_sizes[1] / 2;
    const int* srcp = ei;
    const int* dstp = ei + e;

    // one-time side stream + events (created on the non-captured correctness call)
    static cudaStream_t s2 = [] { cudaStream_t s; cudaStreamCreate(&s); return s; }();
    static cudaEvent_t evA = [] { cudaEvent_t ev; cudaEventCreateWithFlags(&ev, cudaEventDisableTiming); return ev; }();
    static cudaEvent_t evB = [] { cudaEvent_t ev; cudaEventCreateWithFlags(&ev, cudaEventDisableTiming); return ev; }();

    const int smemp128 = (2 * 64 * 68 + 2 * 64 * (HH   + 8)) * 4;   // ~102 KB -> 2 CTA/SM
    const int smemp64  = (2 * 64 * 68 + 2 * 64 * (OUTC + 8)) * 4;   // ~70 KB  -> 3 CTA/SM
    cudaFuncSetAttribute((const void*)k_gemm_pre<HH, 1, 1>,
                         cudaFuncAttributeMaxDynamicSharedMemorySize, smemp128);
    cudaFuncSetAttribute((const void*)k_gemm_pre<HH, 0, 2>,
                         cudaFuncAttributeMaxDynamicSharedMemorySize, smemp128);
    cudaFuncSetAttribute((const void*)k_gemm_pre<OUTC, 0, 3>,
                         cudaFuncAttributeMaxDynamicSharedMemorySize, smemp64);

    int nb_scan = (n + 1023) >> 10;
    int gemm_blocks = (n + 63) / 64;
    int agg_blocks  = (int)(((long long)n * 32 + 255) / 256);

    // main: zero -> count -> prep(dinv + all W splits) -> gemm1
    k_zero <<<(n + 255) / 256, 256>>>(n);
    k_count<<<(e + 255) / 256, 256>>>(dstp, e);
    cudaEventRecord(evA, 0);                         // counts ready
    k_prep <<<(n + 255) / 256, 256>>>(W1, W2, W3, n);
    k_gemm_pre<HH, 1, 1><<<gemm_blocks, 256, smemp128>>>(x, n);

    // side: CSR scans + fill, overlapped with gemm1
    cudaStreamWaitEvent(s2, evA, 0);
    k_scan1<<<nb_scan, 1024, 0, s2>>>(n);
    k_scan2<<<1, 128, 0, s2>>>(nb_scan, n);
    k_scan3<<<(n + 255) / 256, 256, 0, s2>>>(n);
    k_fill <<<(e + 255) / 256, 256, 0, s2>>>(srcp, dstp, e);
    cudaEventRecord(evB, s2);
    cudaStreamWaitEvent(0, evB, 0);                  // join before agg1

    // layer 1 aggregate -> packed bf16 activations
    k_agg<HH, 0><<<agg_blocks, 256>>>(b1, nullptr, n);
    // layer 2
    k_gemm_pre<HH, 0, 2><<<gemm_blocks, 256, smemp128>>>(nullptr, n);
    k_agg<HH, 0><<<agg_blocks, 256>>>(b2, nullptr, n);
    // layer 3
    k_gemm_pre<OUTC, 0, 3><<<gemm_blocks, 256, smemp64>>>(nullptr, n);
    k_agg<OUTC, 1><<<agg_blocks, 256>>>(b3, out, n);
}